// round 13
// baseline (speedup 1.0000x reference)
#include <cuda_runtime.h>
#include <cuda_bf16.h>
#include <cstdint>

// Problem constants
#define N_ROWS   8192      // 2 * B * S^3
#define C_DIM    16
#define ESCALE   14.4269504088896340f   // 10 * log2(e): logits/T in log2 domain
#define LN2F     0.69314718055994531f
#define POOL_BLOCKS   4096u            // power of two: mod trick needs no reset
#define LOGITS_ACTIVE 2080u            // 64*65/2 upper-triangle blocks

// Scratch (device globals: no allocation allowed)
__device__ float g_mmA[N_ROWS * C_DIM];      // pool partial (dz 0..3), raw sums
__device__ float g_mmB[N_ROWS * C_DIM];      // pool partial (dz 4..7), raw sums
__device__ __nv_bfloat16 g_fsb[N_ROWS * 32]; // per row: [0:16) hi, [16:32) lo of ESCALE*f
__device__ __nv_bfloat16 g_fub[N_ROWS * 32]; // per row: [0:16) hi, [16:32) lo of f
__device__ float g_rowsum[N_ROWS];           // exp-sum per row (atomic accumulation)
__device__ float g_pos[N_ROWS / 2];          // pos logit per pair (rows 0..4095)
__device__ unsigned int g_done_pool = 0;     // monotonic; mod-4096 per run
__device__ unsigned int g_done_log  = 0;     // reset by the single finisher

// ---------------------------------------------------------------------------
// Kernel 1: AdaptiveAvgPool3d(64->8) + fused project_head/normalize.
// Grid 4096 x 256. Pool phase identical to R10/R11. The last 32 blocks to
// finish (completion counter, mod-4096 wrap-safe) each run one 256-row slice
// of the MLP after spinning until all 4096 blocks have published.
// First 32 blocks also zero g_rowsum.
// ---------------------------------------------------------------------------
__global__ void __launch_bounds__(256) pool_mlp_kernel(const float* __restrict__ p1,
                                                       const float* __restrict__ p2,
                                                       const float* __restrict__ w1,
                                                       const float* __restrict__ b1,
                                                       const float* __restrict__ w2,
                                                       const float* __restrict__ b2)
{
    __shared__ float sw1[256], sw2[256], sb1[16], sb2[16];
    __shared__ unsigned int sOld;

    int bid  = blockIdx.x;           // 0..4095
    int tid  = threadIdx.x;
    if (bid < 32) g_rowsum[bid * 256 + tid] = 0.f;

    int t    = bid >> 11;
    int r    = bid & 2047;
    int b    = r >> 8;
    int c    = (r >> 4) & 15;
    int sd   = (r >> 1) & 7;
    int half = r & 1;

    const float* p = t ? p2 : p1;
    int sh     = tid >> 5;
    int lane   = tid & 31;
    int rowsel = lane >> 4;
    int wid4   = lane & 15;

    const float4* base = (const float4*)(p + ((((b << 4) + c) * 64 + (sd << 3) + (half << 2)) << 12)
                                           + (sh << 3) * 64);

    float acc = 0.f;
#pragma unroll
    for (int dz = 0; dz < 4; dz++) {
#pragma unroll
        for (int hp = 0; hp < 4; hp++) {
            float4 v = base[dz * 1024 + (hp * 2 + rowsel) * 16 + wid4];
            acc += (v.x + v.y) + (v.z + v.w);
        }
    }
    acc += __shfl_xor_sync(0xffffffffu, acc, 1);
    acc += __shfl_xor_sync(0xffffffffu, acc, 16);

    if (((lane & 1) == 0) && lane < 16) {
        int sx  = lane >> 1;
        int row = t * 4096 + b * 512 + sd * 64 + sh * 8 + sx;
        float* dst = half ? g_mmB : g_mmA;
        dst[row * C_DIM + c] = acc;
    }

    // ---- publish + completion count ----
    __threadfence();
    __syncthreads();
    if (tid == 0) sOld = atomicAdd(&g_done_pool, 1u);
    __syncthreads();
    unsigned int om = sOld & (POOL_BLOCKS - 1u);   // arrival index within this run
    if (om < POOL_BLOCKS - 32u) return;

    // ---- MLP phase: last 32 arrivals; wait until all 4096 published ----
    if (tid == 0) {
        volatile unsigned int* cp = &g_done_pool;
        while ((*cp & (POOL_BLOCKS - 1u)) != 0u) { __nanosleep(32); }
    }
    __syncthreads();
    __threadfence();

    sw1[tid] = w1[tid];
    sw2[tid] = w2[tid];
    if (tid < 16) { sb1[tid] = b1[tid]; sb2[tid] = b2[tid]; }
    __syncthreads();

    int row = (int)(om - (POOL_BLOCKS - 32u)) * 256 + tid;

    float x[16];
    const float4* ma4 = (const float4*)(g_mmA + row * C_DIM);
    const float4* mb4 = (const float4*)(g_mmB + row * C_DIM);
#pragma unroll
    for (int q = 0; q < 4; q++) {
        float4 va = ma4[q], vb = mb4[q];
        x[q * 4 + 0] = (va.x + vb.x) * (1.0f / 512.0f);
        x[q * 4 + 1] = (va.y + vb.y) * (1.0f / 512.0f);
        x[q * 4 + 2] = (va.z + vb.z) * (1.0f / 512.0f);
        x[q * 4 + 3] = (va.w + vb.w) * (1.0f / 512.0f);
    }

    float h[16];
#pragma unroll
    for (int k = 0; k < 16; k++) {
        float s = sb1[k];
#pragma unroll
        for (int cc = 0; cc < 16; cc++) s = fmaf(sw1[k * 16 + cc], x[cc], s);
        h[k] = fmaxf(s, 0.f);
    }

    float f[16];
    float nsq = 0.f;
#pragma unroll
    for (int k = 0; k < 16; k++) {
        float s = sb2[k];
#pragma unroll
        for (int cc = 0; cc < 16; cc++) s = fmaf(sw2[k * 16 + cc], h[cc], s);
        f[k] = s;
        nsq = fmaf(s, s, nsq);
    }
    float inv = 1.0f / fmaxf(sqrtf(nsq), 1e-12f);

    __nv_bfloat16* fsb = g_fsb + row * 32;
    __nv_bfloat16* fub = g_fub + row * 32;
#pragma unroll
    for (int k = 0; k < 16; k++) {
        float u = f[k] * inv;
        float s = u * ESCALE;
        __nv_bfloat16 sh2 = __float2bfloat16(s);
        fsb[k]      = sh2;
        fsb[16 + k] = __float2bfloat16(s - __bfloat162float(sh2));
        __nv_bfloat16 uh = __float2bfloat16(u);
        fub[k]      = uh;
        fub[16 + k] = __float2bfloat16(u - __bfloat162float(uh));
    }
}

// ---------------------------------------------------------------------------
// Warp-MMA helpers (baseline PTX: mma.sync + ldmatrix, sm_80+)
// ---------------------------------------------------------------------------
static __device__ __forceinline__ float ex2_approx(float x)
{
    float r;
    asm("ex2.approx.f32 %0, %1;" : "=f"(r) : "f"(x));
    return r;
}
static __device__ __forceinline__ uint32_t smem_u32(const void* p)
{
    return (uint32_t)__cvta_generic_to_shared(p);
}
static __device__ __forceinline__ void ldsm_x4(uint32_t* f, uint32_t addr)
{
    asm volatile("ldmatrix.sync.aligned.m8n8.x4.shared.b16 {%0,%1,%2,%3}, [%4];"
                 : "=r"(f[0]), "=r"(f[1]), "=r"(f[2]), "=r"(f[3]) : "r"(addr));
}
static __device__ __forceinline__ void mma_bf16(float* d, const uint32_t* a, const uint32_t* b)
{
    asm volatile("mma.sync.aligned.m16n8k16.row.col.f32.bf16.bf16.f32 "
                 "{%0,%1,%2,%3}, {%4,%5,%6,%7}, {%8,%9}, {%0,%1,%2,%3};"
                 : "+f"(d[0]), "+f"(d[1]), "+f"(d[2]), "+f"(d[3])
                 : "r"(a[0]), "r"(a[1]), "r"(a[2]), "r"(a[3]), "r"(b[0]), "r"(b[1]));
}

#define SROW 80   // smem row stride (bytes): 16B-aligned, conflict-free for ldmatrix

// ---------------------------------------------------------------------------
// Kernel 2: logits exp-sums via symmetric split-bf16 tensor-core MMA, with
// the final loss reduction fused into the LAST finishing block.
// Grid (64, 64) x 128; lower-triangle blocks (jb < ib) exit immediately.
// Off-diagonal tiles computed ONCE (symmetry feeds row AND column sums).
// Blocks with jb == ib+32 harvest the positive-pair logits. The 2080th
// active block to finish reduces all rows -> out[0], resets the counter.
// ---------------------------------------------------------------------------
__global__ void __launch_bounds__(128) logits_mma_kernel(float* __restrict__ out)
{
    __shared__ __align__(16) unsigned char smA[128 * SROW];
    __shared__ __align__(16) unsigned char smB[128 * SROW];
    __shared__ float wred[4];
    __shared__ bool sLast;

    int ib  = blockIdx.x;
    int jb  = blockIdx.y;
    if (jb < ib) return;
    bool diag = (ib == jb);
    bool posb = (jb == ib + 32);

    int tid = threadIdx.x;
    int w   = tid >> 5;
    int l   = tid & 31;

    // Stage one A row + one B row per thread (64 B each: 16 hi + 16 lo bf16)
    {
        const uint4* srcA = (const uint4*)(g_fsb + (ib * 128 + tid) * 32);
        const uint4* srcB = (const uint4*)(g_fub + (jb * 128 + tid) * 32);
#pragma unroll
        for (int q = 0; q < 4; q++) *(uint4*)(smA + tid * SROW + q * 16) = srcA[q];
#pragma unroll
        for (int q = 0; q < 4; q++) *(uint4*)(smB + tid * SROW + q * 16) = srcB[q];
    }
    __syncthreads();

    // A fragments for this warp's two 16-row m-tiles, hi and lo terms.
    uint32_t Ah[2][4], Al[2][4];
    {
        int r  = (l & 7) + ((l >> 3) & 1) * 8;
        int kh = l >> 4;
#pragma unroll
        for (int mt = 0; mt < 2; mt++) {
            uint32_t a = smem_u32(smA + (w * 32 + mt * 16 + r) * SROW + kh * 16);
            ldsm_x4(Ah[mt], a);
            ldsm_x4(Al[mt], a + 32);
        }
    }

    float P0 = 0.f, P1 = 0.f, P2 = 0.f, P3 = 0.f;   // rows g, g+8, 16+g, 24+g
    int g = l >> 2;

    // B ldsm_x4: matrix (l>>3) -> k-chunk offset, row (l&7):
    // bf[0..1] = hi k-halves, bf[2..3] = lo k-halves in ONE ldmatrix.
    uint32_t boff = (uint32_t)((l & 7) * SROW + ((l >> 3) << 4));

#pragma unroll 2
    for (int nt = 0; nt < 16; nt++) {
        uint32_t bf[4];
        ldsm_x4(bf, smem_u32(smB + nt * 8 * SROW) + boff);

        float ca0 = 0.f, ca1 = 0.f;   // column sums for cols c0, c0+1

#pragma unroll
        for (int mt = 0; mt < 2; mt++) {
            float d[4] = {0.f, 0.f, 0.f, 0.f};
            mma_bf16(d, Ah[mt], bf);       // ah * bh
            mma_bf16(d, Ah[mt], bf + 2);   // ah * bl
            mma_bf16(d, Al[mt], bf);       // al * bh

            int lcol0 = nt * 8 + (l & 3) * 2;
            int lrow0 = w * 32 + mt * 16 + g;

            if (posb) {
                if (lrow0 == lcol0)         g_pos[ib * 128 + lrow0]     = d[0] * LN2F;
                if (lrow0 == lcol0 + 1)     g_pos[ib * 128 + lrow0]     = d[1] * LN2F;
                if (lrow0 + 8 == lcol0)     g_pos[ib * 128 + lrow0 + 8] = d[2] * LN2F;
                if (lrow0 + 8 == lcol0 + 1) g_pos[ib * 128 + lrow0 + 8] = d[3] * LN2F;
            }

            float e0 = ex2_approx(d[0]);
            float e1 = ex2_approx(d[1]);
            float e2 = ex2_approx(d[2]);
            float e3 = ex2_approx(d[3]);

            if (diag) {
                if (lrow0 == lcol0)         e0 = 0.f;
                if (lrow0 == lcol0 + 1)     e1 = 0.f;
                if (lrow0 + 8 == lcol0)     e2 = 0.f;
                if (lrow0 + 8 == lcol0 + 1) e3 = 0.f;
            }
            if (mt == 0) { P0 += e0 + e1; P1 += e2 + e3; }
            else         { P2 += e0 + e1; P3 += e2 + e3; }

            ca0 += e0 + e2;
            ca1 += e1 + e3;
        }

        if (!diag) {
            ca0 += __shfl_xor_sync(0xffffffffu, ca0, 4);
            ca0 += __shfl_xor_sync(0xffffffffu, ca0, 8);
            ca0 += __shfl_xor_sync(0xffffffffu, ca0, 16);
            ca1 += __shfl_xor_sync(0xffffffffu, ca1, 4);
            ca1 += __shfl_xor_sync(0xffffffffu, ca1, 8);
            ca1 += __shfl_xor_sync(0xffffffffu, ca1, 16);
            if (l < 4) {
                int colbase = jb * 128 + nt * 8 + l * 2;
                atomicAdd(&g_rowsum[colbase],     ca0);
                atomicAdd(&g_rowsum[colbase + 1], ca1);
            }
        }
    }

    P0 += __shfl_xor_sync(0xffffffffu, P0, 1);
    P0 += __shfl_xor_sync(0xffffffffu, P0, 2);
    P1 += __shfl_xor_sync(0xffffffffu, P1, 1);
    P1 += __shfl_xor_sync(0xffffffffu, P1, 2);
    P2 += __shfl_xor_sync(0xffffffffu, P2, 1);
    P2 += __shfl_xor_sync(0xffffffffu, P2, 2);
    P3 += __shfl_xor_sync(0xffffffffu, P3, 1);
    P3 += __shfl_xor_sync(0xffffffffu, P3, 2);

    if ((l & 3) == 0) {
        int rowbase = ib * 128 + w * 32;
        atomicAdd(&g_rowsum[rowbase + g],      P0);
        atomicAdd(&g_rowsum[rowbase + 8 + g],  P1);
        atomicAdd(&g_rowsum[rowbase + 16 + g], P2);
        atomicAdd(&g_rowsum[rowbase + 24 + g], P3);
    }

    // ---- fused final reduction: single last-finishing block ----
    __threadfence();
    __syncthreads();
    if (tid == 0) sLast = (atomicAdd(&g_done_log, 1u) == LOGITS_ACTIVE - 1u);
    __syncthreads();
    if (!sLast) return;

    __threadfence();
    float acc = 0.f;
    for (int i = tid; i < N_ROWS; i += 128)
        acc += logf(g_rowsum[i]) - g_pos[i & 4095];

    acc += __shfl_xor_sync(0xffffffffu, acc, 16);
    acc += __shfl_xor_sync(0xffffffffu, acc, 8);
    acc += __shfl_xor_sync(0xffffffffu, acc, 4);
    acc += __shfl_xor_sync(0xffffffffu, acc, 2);
    acc += __shfl_xor_sync(0xffffffffu, acc, 1);
    if ((tid & 31) == 0) wred[tid >> 5] = acc;
    __syncthreads();
    if (tid == 0) {
        out[0] = ((wred[0] + wred[1]) + (wred[2] + wred[3])) * (1.0f / (float)N_ROWS);
        g_done_log = 0;   // reset for next graph replay
    }
}

// ---------------------------------------------------------------------------
extern "C" void kernel_launch(void* const* d_in, const int* in_sizes, int n_in,
                              void* d_out, int out_size)
{
    const float* p1 = (const float*)d_in[0];
    const float* p2 = (const float*)d_in[1];
    const float* w1 = (const float*)d_in[2];
    const float* b1 = (const float*)d_in[3];
    const float* w2 = (const float*)d_in[4];
    const float* b2 = (const float*)d_in[5];

    pool_mlp_kernel<<<POOL_BLOCKS, 256>>>(p1, p2, w1, b1, w2, b2);
    logits_mma_kernel<<<dim3(64, 64), 128>>>((float*)d_out);
}

// round 14
// speedup vs baseline: 1.4151x; 1.4151x over previous
#include <cuda_runtime.h>
#include <cuda_bf16.h>
#include <cstdint>

// Problem constants
#define N_ROWS   8192      // 2 * B * S^3
#define C_DIM    16
#define ESCALE   14.4269504088896340f   // 10 * log2(e): logits/T in log2 domain
#define LN2F     0.69314718055994531f

// Scratch (device globals: no allocation allowed)
__device__ float g_mmA[N_ROWS * C_DIM];      // pool partial (dz 0..3), raw sums
__device__ float g_mmB[N_ROWS * C_DIM];      // pool partial (dz 4..7), raw sums
__device__ __nv_bfloat16 g_fsb[N_ROWS * 32]; // per row: [0:16) hi, [16:32) lo of ESCALE*f
__device__ __nv_bfloat16 g_fub[N_ROWS * 32]; // per row: [0:16) hi, [16:32) lo of f
__device__ float g_rowsum[N_ROWS];           // exp-sum per row (atomic accumulation)
__device__ float g_pos[N_ROWS / 2];          // pos logit per pair (rows 0..4095)
__device__ float g_blocksum[32];
__device__ unsigned int g_done = 0;

// ---------------------------------------------------------------------------
// Kernel 1: AdaptiveAvgPool3d(64->8), split over dz halves (R12 form).
// First 32 blocks also zero g_rowsum (completes before logits launch).
// ---------------------------------------------------------------------------
__global__ void __launch_bounds__(256) pool_kernel(const float* __restrict__ p1,
                                                   const float* __restrict__ p2)
{
    int bid  = blockIdx.x;           // 0..4095
    int tid  = threadIdx.x;
    if (bid < 32) g_rowsum[bid * 256 + tid] = 0.f;

    int t    = bid >> 11;
    int r    = bid & 2047;
    int b    = r >> 8;
    int c    = (r >> 4) & 15;
    int sd   = (r >> 1) & 7;
    int half = r & 1;

    const float* p = t ? p2 : p1;
    int sh     = tid >> 5;
    int lane   = tid & 31;
    int rowsel = lane >> 4;
    int wid4   = lane & 15;

    const float4* base = (const float4*)(p + ((((b << 4) + c) * 64 + (sd << 3) + (half << 2)) << 12)
                                           + (sh << 3) * 64);

    float acc = 0.f;
#pragma unroll
    for (int dz = 0; dz < 4; dz++) {
#pragma unroll
        for (int hp = 0; hp < 4; hp++) {
            float4 v = base[dz * 1024 + (hp * 2 + rowsel) * 16 + wid4];
            acc += (v.x + v.y) + (v.z + v.w);
        }
    }
    acc += __shfl_xor_sync(0xffffffffu, acc, 1);
    acc += __shfl_xor_sync(0xffffffffu, acc, 16);

    if (((lane & 1) == 0) && lane < 16) {
        int sx  = lane >> 1;
        int row = t * 4096 + b * 512 + sd * 64 + sh * 8 + sx;
        float* dst = half ? g_mmB : g_mmA;
        dst[row * C_DIM + c] = acc;
    }
}

// ---------------------------------------------------------------------------
// Kernel 2: combine pool halves + project_head + F.normalize per row.
// Emits split-bf16 (hi+lo) MMA operand arrays (pos comes from the MMA).
// ---------------------------------------------------------------------------
__global__ void __launch_bounds__(256) mlp_kernel(const float* __restrict__ w1,
                                                  const float* __restrict__ b1,
                                                  const float* __restrict__ w2,
                                                  const float* __restrict__ b2)
{
    __shared__ float sw1[256], sw2[256], sb1[16], sb2[16];
    int tid = threadIdx.x;
    sw1[tid] = w1[tid];
    sw2[tid] = w2[tid];
    if (tid < 16) { sb1[tid] = b1[tid]; sb2[tid] = b2[tid]; }
    __syncthreads();

    int row = blockIdx.x * 256 + tid;

    float x[16];
    const float4* ma4 = (const float4*)(g_mmA + row * C_DIM);
    const float4* mb4 = (const float4*)(g_mmB + row * C_DIM);
#pragma unroll
    for (int q = 0; q < 4; q++) {
        float4 va = ma4[q], vb = mb4[q];
        x[q * 4 + 0] = (va.x + vb.x) * (1.0f / 512.0f);
        x[q * 4 + 1] = (va.y + vb.y) * (1.0f / 512.0f);
        x[q * 4 + 2] = (va.z + vb.z) * (1.0f / 512.0f);
        x[q * 4 + 3] = (va.w + vb.w) * (1.0f / 512.0f);
    }

    float h[16];
#pragma unroll
    for (int k = 0; k < 16; k++) {
        float s = sb1[k];
#pragma unroll
        for (int cc = 0; cc < 16; cc++) s = fmaf(sw1[k * 16 + cc], x[cc], s);
        h[k] = fmaxf(s, 0.f);
    }

    float f[16];
    float nsq = 0.f;
#pragma unroll
    for (int k = 0; k < 16; k++) {
        float s = sb2[k];
#pragma unroll
        for (int cc = 0; cc < 16; cc++) s = fmaf(sw2[k * 16 + cc], h[cc], s);
        f[k] = s;
        nsq = fmaf(s, s, nsq);
    }
    float inv = 1.0f / fmaxf(sqrtf(nsq), 1e-12f);

    __nv_bfloat16* fsb = g_fsb + row * 32;
    __nv_bfloat16* fub = g_fub + row * 32;
#pragma unroll
    for (int k = 0; k < 16; k++) {
        float u = f[k] * inv;
        float s = u * ESCALE;
        __nv_bfloat16 sh = __float2bfloat16(s);
        fsb[k]      = sh;
        fsb[16 + k] = __float2bfloat16(s - __bfloat162float(sh));
        __nv_bfloat16 uh = __float2bfloat16(u);
        fub[k]      = uh;
        fub[16 + k] = __float2bfloat16(u - __bfloat162float(uh));
    }
}

// ---------------------------------------------------------------------------
// Warp-MMA helpers (baseline PTX: mma.sync + ldmatrix, sm_80+)
// ---------------------------------------------------------------------------
static __device__ __forceinline__ float ex2_approx(float x)
{
    float r;
    asm("ex2.approx.f32 %0, %1;" : "=f"(r) : "f"(x));
    return r;
}
static __device__ __forceinline__ uint32_t smem_u32(const void* p)
{
    return (uint32_t)__cvta_generic_to_shared(p);
}
static __device__ __forceinline__ void ldsm_x4(uint32_t* f, uint32_t addr)
{
    asm volatile("ldmatrix.sync.aligned.m8n8.x4.shared.b16 {%0,%1,%2,%3}, [%4];"
                 : "=r"(f[0]), "=r"(f[1]), "=r"(f[2]), "=r"(f[3]) : "r"(addr));
}
static __device__ __forceinline__ void mma_bf16(float* d, const uint32_t* a, const uint32_t* b)
{
    asm volatile("mma.sync.aligned.m16n8k16.row.col.f32.bf16.bf16.f32 "
                 "{%0,%1,%2,%3}, {%4,%5,%6,%7}, {%8,%9}, {%0,%1,%2,%3};"
                 : "+f"(d[0]), "+f"(d[1]), "+f"(d[2]), "+f"(d[3])
                 : "r"(a[0]), "r"(a[1]), "r"(a[2]), "r"(a[3]), "r"(b[0]), "r"(b[1]));
}

#define SROW 80   // smem row stride (bytes): 16B-aligned, conflict-free for ldmatrix

// ---------------------------------------------------------------------------
// Kernel 3: logits exp-sums via symmetric split-bf16 tensor-core MMA.
// 256x256 tiles, 256 threads (8 warps x 32 rows). Grid (32, 32); lower
// triangle exits. 528 active blocks ~= one wave at 4 blocks/SM. Off-diagonal
// tiles computed ONCE (symmetry feeds row AND column sums); jb == ib+16
// blocks harvest the positive-pair logits (tile-local diagonal = i,i+4096).
// ---------------------------------------------------------------------------
__global__ void __launch_bounds__(256) logits_mma_kernel()
{
    __shared__ __align__(16) unsigned char smA[256 * SROW];   // 20 KB
    __shared__ __align__(16) unsigned char smB[256 * SROW];   // 20 KB

    int ib  = blockIdx.x;
    int jb  = blockIdx.y;
    if (jb < ib) return;
    bool diag = (ib == jb);
    bool posb = (jb == ib + 16);

    int tid = threadIdx.x;
    int w   = tid >> 5;          // 0..7: warp owns rows [32w, 32w+32)
    int l   = tid & 31;

    // Stage one A row + one B row per thread (64 B each: 16 hi + 16 lo bf16)
    {
        const uint4* srcA = (const uint4*)(g_fsb + (ib * 256 + tid) * 32);
        const uint4* srcB = (const uint4*)(g_fub + (jb * 256 + tid) * 32);
#pragma unroll
        for (int q = 0; q < 4; q++) *(uint4*)(smA + tid * SROW + q * 16) = srcA[q];
#pragma unroll
        for (int q = 0; q < 4; q++) *(uint4*)(smB + tid * SROW + q * 16) = srcB[q];
    }
    __syncthreads();

    // A fragments for this warp's two 16-row m-tiles, hi and lo terms.
    uint32_t Ah[2][4], Al[2][4];
    {
        int r  = (l & 7) + ((l >> 3) & 1) * 8;
        int kh = l >> 4;
#pragma unroll
        for (int mt = 0; mt < 2; mt++) {
            uint32_t a = smem_u32(smA + (w * 32 + mt * 16 + r) * SROW + kh * 16);
            ldsm_x4(Ah[mt], a);
            ldsm_x4(Al[mt], a + 32);
        }
    }

    float P0 = 0.f, P1 = 0.f, P2 = 0.f, P3 = 0.f;   // rows g, g+8, 16+g, 24+g
    int g = l >> 2;

    // B ldsm_x4: matrix (l>>3) -> k-chunk offset, row (l&7):
    // bf[0..1] = hi k-halves, bf[2..3] = lo k-halves in ONE ldmatrix.
    uint32_t boff = (uint32_t)((l & 7) * SROW + ((l >> 3) << 4));

#pragma unroll 2
    for (int nt = 0; nt < 32; nt++) {
        uint32_t bf[4];
        ldsm_x4(bf, smem_u32(smB + nt * 8 * SROW) + boff);

        float ca0 = 0.f, ca1 = 0.f;   // column sums for cols c0, c0+1

#pragma unroll
        for (int mt = 0; mt < 2; mt++) {
            float d[4] = {0.f, 0.f, 0.f, 0.f};
            mma_bf16(d, Ah[mt], bf);       // ah * bh
            mma_bf16(d, Ah[mt], bf + 2);   // ah * bl
            mma_bf16(d, Al[mt], bf);       // al * bh

            int lcol0 = nt * 8 + (l & 3) * 2;
            int lrow0 = w * 32 + mt * 16 + g;

            if (posb) {
                // tile-local diagonal = (i, i+4096) positive pairs
                if (lrow0 == lcol0)         g_pos[ib * 256 + lrow0]     = d[0] * LN2F;
                if (lrow0 == lcol0 + 1)     g_pos[ib * 256 + lrow0]     = d[1] * LN2F;
                if (lrow0 + 8 == lcol0)     g_pos[ib * 256 + lrow0 + 8] = d[2] * LN2F;
                if (lrow0 + 8 == lcol0 + 1) g_pos[ib * 256 + lrow0 + 8] = d[3] * LN2F;
            }

            float e0 = ex2_approx(d[0]);
            float e1 = ex2_approx(d[1]);
            float e2 = ex2_approx(d[2]);
            float e3 = ex2_approx(d[3]);

            if (diag) {
                if (lrow0 == lcol0)         e0 = 0.f;
                if (lrow0 == lcol0 + 1)     e1 = 0.f;
                if (lrow0 + 8 == lcol0)     e2 = 0.f;
                if (lrow0 + 8 == lcol0 + 1) e3 = 0.f;
            }
            if (mt == 0) { P0 += e0 + e1; P1 += e2 + e3; }
            else         { P2 += e0 + e1; P3 += e2 + e3; }

            ca0 += e0 + e2;
            ca1 += e1 + e3;
        }

        if (!diag) {
            // reduce column sums over the 8 g-groups (lane bits 2,3,4)
            ca0 += __shfl_xor_sync(0xffffffffu, ca0, 4);
            ca0 += __shfl_xor_sync(0xffffffffu, ca0, 8);
            ca0 += __shfl_xor_sync(0xffffffffu, ca0, 16);
            ca1 += __shfl_xor_sync(0xffffffffu, ca1, 4);
            ca1 += __shfl_xor_sync(0xffffffffu, ca1, 8);
            ca1 += __shfl_xor_sync(0xffffffffu, ca1, 16);
            if (l < 4) {
                int colbase = jb * 256 + nt * 8 + l * 2;
                atomicAdd(&g_rowsum[colbase],     ca0);
                atomicAdd(&g_rowsum[colbase + 1], ca1);
            }
        }
    }

    // Reduce row sums across the 4 lanes of each quad, accumulate atomically
    P0 += __shfl_xor_sync(0xffffffffu, P0, 1);
    P0 += __shfl_xor_sync(0xffffffffu, P0, 2);
    P1 += __shfl_xor_sync(0xffffffffu, P1, 1);
    P1 += __shfl_xor_sync(0xffffffffu, P1, 2);
    P2 += __shfl_xor_sync(0xffffffffu, P2, 1);
    P2 += __shfl_xor_sync(0xffffffffu, P2, 2);
    P3 += __shfl_xor_sync(0xffffffffu, P3, 1);
    P3 += __shfl_xor_sync(0xffffffffu, P3, 2);

    if ((l & 3) == 0) {
        int rowbase = ib * 256 + w * 32;
        atomicAdd(&g_rowsum[rowbase + g],      P0);
        atomicAdd(&g_rowsum[rowbase + 8 + g],  P1);
        atomicAdd(&g_rowsum[rowbase + 16 + g], P2);
        atomicAdd(&g_rowsum[rowbase + 24 + g], P3);
    }
}

// ---------------------------------------------------------------------------
// Kernel 4: per-row loss = log(rowsum) - pos; deterministic-order reductions,
// last-block combine (counter self-resets for graph replay).
// ---------------------------------------------------------------------------
__global__ void __launch_bounds__(256) final_kernel(float* __restrict__ out)
{
    __shared__ float red[8];
    __shared__ bool is_last;
    int tid = threadIdx.x;
    int i   = blockIdx.x * 256 + tid;

    float S   = g_rowsum[i];
    float pos = g_pos[i & 4095];

    float v = logf(S) - pos;
    v += __shfl_xor_sync(0xffffffffu, v, 16);
    v += __shfl_xor_sync(0xffffffffu, v, 8);
    v += __shfl_xor_sync(0xffffffffu, v, 4);
    v += __shfl_xor_sync(0xffffffffu, v, 2);
    v += __shfl_xor_sync(0xffffffffu, v, 1);
    if ((tid & 31) == 0) red[tid >> 5] = v;
    __syncthreads();

    if (tid == 0) {
        float t = 0.f;
#pragma unroll
        for (int q = 0; q < 8; q++) t += red[q];
        g_blocksum[blockIdx.x] = t;
        __threadfence();
        unsigned int done = atomicAdd(&g_done, 1u);
        is_last = (done == 31u);
    }
    __syncthreads();

    if (is_last && tid < 32) {
        float u = g_blocksum[tid];
#pragma unroll
        for (int s = 16; s > 0; s >>= 1) u += __shfl_xor_sync(0xffffffffu, u, s);
        if (tid == 0) {
            out[0] = u * (1.0f / (float)N_ROWS);
            g_done = 0;
        }
    }
}

// ---------------------------------------------------------------------------
extern "C" void kernel_launch(void* const* d_in, const int* in_sizes, int n_in,
                              void* d_out, int out_size)
{
    const float* p1 = (const float*)d_in[0];
    const float* p2 = (const float*)d_in[1];
    const float* w1 = (const float*)d_in[2];
    const float* b1 = (const float*)d_in[3];
    const float* w2 = (const float*)d_in[4];
    const float* b2 = (const float*)d_in[5];

    pool_kernel<<<4096, 256>>>(p1, p2);
    mlp_kernel<<<32, 256>>>(w1, b1, w2, b2);
    logits_mma_kernel<<<dim3(32, 32), 256>>>();
    final_kernel<<<32, 256>>>((float*)d_out);
}